// round 9
// baseline (speedup 1.0000x reference)
#include <cuda_runtime.h>
#include <cuda_fp16.h>
#include <cstdint>

#define BB 32
#define CC 64
#define HH 64
#define WW 64
#define EE 8
#define HWC (HH*WW)

// Scratch (device globals: no allocation allowed)
__device__ float        g_S[BB * 9 * CC];   // box sums [(b*9+k)*64+c], k=di*3+dj
__device__ int          g_cnt[BB];
__device__ volatile int g_flag[BB];
__device__ float        g_val[BB];
__device__ int          g_idx[BB];

// ===========================================================================
// helpers
// ===========================================================================
__device__ __forceinline__ uint32_t smem_u32(const void* p) {
    uint32_t a;
    asm("{ .reg .u64 t; cvta.to.shared.u64 t, %1; cvt.u32.u64 %0, t; }" : "=r"(a) : "l"(p));
    return a;
}

__device__ __forceinline__ uint32_t pack_f16x2(float even, float odd) {
    __half2 h = __floats2half2_rn(even, odd);
    return *reinterpret_cast<uint32_t*>(&h);
}

#define LDMATRIX_X2T(R, addr) \
    asm volatile("ldmatrix.sync.aligned.m8n8.x2.trans.shared.b16 {%0,%1}, [%2];" \
        : "=r"((R)[0]), "=r"((R)[1]) : "r"(addr))

#define MMA_F16(D, A, B0, B1) \
    asm volatile("mma.sync.aligned.m16n8k16.row.col.f32.f16.f16.f32 " \
        "{%0,%1,%2,%3}, {%4,%5,%6,%7}, {%8,%9}, {%0,%1,%2,%3};" \
        : "+f"((D)[0]), "+f"((D)[1]), "+f"((D)[2]), "+f"((D)[3]) \
        : "r"((A)[0]), "r"((A)[1]), "r"((A)[2]), "r"((A)[3]), "r"(B0), "r"(B1))

// ===========================================================================
// Kernel 0: zero the cross-block scratch (must be fresh every launch)
// ===========================================================================
__global__ void zero_kernel() {
    int i = blockIdx.x * blockDim.x + threadIdx.x;
    const int n = BB * 9 * CC;
    for (int j = i; j < n; j += gridDim.x * blockDim.x) g_S[j] = 0.f;
    if (i < BB) { g_cnt[i] = 0; g_flag[i] = 0; }
}

// ===========================================================================
// Fused kernel, v2: x read ONCE, loads batched (MLP=8), 256 threads.
// Grid (chunk, b); block tile = [c=64][hw=128] (image rows 2*chunk, 2*chunk+1).
// Phase 1: 8 batched LDG.128/thread -> stats + fp16 smem stage.
// Gate:    last block per b computes softmax/top-1, publishes val/idx.
// Phase 2: fp16 mma.sync GEMM (8 warps, 16f x 64hw per warp).
// ===========================================================================
#define XPITCH 68u   // words per X row (64 data words + 4 pad)

__global__ __launch_bounds__(256) void fused_kernel(const float* __restrict__ x,
                                                    const float* __restrict__ expert_w,
                                                    const float* __restrict__ gate_w,
                                                    const float* __restrict__ gate_b,
                                                    float* __restrict__ out,
                                                    int write_ew) {
    __shared__ uint32_t sX[64 * XPITCH];     // fp16x2 X tile
    __shared__ float sCvA[64][3], sCvB[64][3];
    __shared__ float sGat[8];
    __shared__ float shv;
    __shared__ int   she, shLast;

    const int tid   = threadIdx.x;
    const int warp  = tid >> 5, lane = tid & 31;
    const int chunk = blockIdx.x;            // image rows 2*chunk, 2*chunk+1
    const int b     = blockIdx.y;
    const int hw0   = chunk * 128;

    const float* Xsrc = x + (size_t)b * CC * HWC + hw0;

    // ---- Phase 1a: batched loads. Warp w, iter j -> channel row c = j*8 + w,
    //      lane = float4 within the 128-float row (one warp instr = 512B). ----
    float4 v[8];
    #pragma unroll
    for (int j = 0; j < 8; j++) {
        int c = j * 8 + warp;
        v[j] = *(const float4*)(Xsrc + (size_t)c * HWC + lane * 4);
    }

    // ---- Phase 1b: convert+store and per-row stats (loads already in regs) ----
    #pragma unroll
    for (int j = 0; j < 8; j++) {
        int c = j * 8 + warp;
        uint2 wv;
        wv.x = pack_f16x2(v[j].x, v[j].y);
        wv.y = pack_f16x2(v[j].z, v[j].w);
        *(uint2*)(sX + c * XPITCH + lane * 2) = wv;

        float ps = (v[j].x + v[j].y) + (v[j].z + v[j].w);
        #pragma unroll
        for (int o = 8; o; o >>= 1) ps += __shfl_xor_sync(0xffffffffu, ps, o);  // 16-lane halves
        int srcL = lane & 16;
        float e0  = __shfl_sync(0xffffffffu, v[j].x, srcL);        // x[r][0]
        float e1  = __shfl_sync(0xffffffffu, v[j].y, srcL);        // x[r][1]
        float e62 = __shfl_sync(0xffffffffu, v[j].z, srcL + 15);   // x[r][62]
        float e63 = __shfl_sync(0xffffffffu, v[j].w, srcL + 15);   // x[r][63]
        if ((lane & 15) == 0) {
            float* dst = (lane < 16) ? sCvA[c] : sCvB[c];
            dst[0] = ps - e62 - e63;   // cols 0..61
            dst[1] = ps - e0  - e63;   // cols 1..62
            dst[2] = ps - e0  - e1;    // cols 2..63
        }
    }
    __syncthreads();

    // ---- box-sum contribution (2 image rows x 64 channels x 9 offsets) ----
    {
        int r0 = chunk * 2, r1 = r0 + 1;
        float mA[3] = { (r0 <= 61) ? 1.f : 0.f, (r0 >= 1 && r0 <= 62) ? 1.f : 0.f, (r0 >= 2) ? 1.f : 0.f };
        float mB[3] = { (r1 <= 61) ? 1.f : 0.f, (r1 >= 1 && r1 <= 62) ? 1.f : 0.f, (r1 >= 2) ? 1.f : 0.f };
        #pragma unroll
        for (int p = 0; p < 3; p++) {
            int j = tid + p * 256;
            if (j < 576) {
                int k = j >> 6, c = j & 63;      // k = di*3+dj
                int di = k / 3, dj = k - di * 3;
                float contrib = mA[di] * sCvA[c][dj] + mB[di] * sCvB[c][dj];
                atomicAdd(&g_S[(b * 9 + k) * CC + c], contrib);
            }
        }
    }
    __syncthreads();
    if (tid == 0) {
        __threadfence();
        int old = atomicAdd(&g_cnt[b], 1);
        shLast = (old == 31);
    }
    __syncthreads();

    if (shLast) {
        // ---- gate: warp = expert ----
        __threadfence();
        float a0 = 0.f;
        for (int idx = lane; idx < 576; idx += 32) {
            int c = idx / 9, k = idx - c * 9;
            float s = __ldcg(&g_S[(b * 9 + k) * CC + c]);
            a0 += gate_w[warp * 576 + idx] * s;
        }
        #pragma unroll
        for (int o = 16; o; o >>= 1) a0 += __shfl_down_sync(0xffffffffu, a0, o);
        if (lane == 0) sGat[warp] = a0 + gate_b[warp] * 3844.0f;
        __syncthreads();
        if (tid == 0) {
            float m = sGat[0]; int mi = 0;
            #pragma unroll
            for (int e2 = 1; e2 < 8; e2++) { if (sGat[e2] > m) { m = sGat[e2]; mi = e2; } }
            float s = 0.f;
            #pragma unroll
            for (int e2 = 0; e2 < 8; e2++) s += expf(sGat[e2] - m);
            float v_ = 1.0f / s;
            g_val[b] = v_;
            g_idx[b] = mi;
            shv = v_; she = mi;
            if (write_ew) {
                float* ew = out + BB * CC * HWC + b * 8;
                #pragma unroll
                for (int e2 = 0; e2 < 8; e2++) ew[e2] = (e2 == mi) ? v_ : 0.0f;
            }
            __threadfence();
            g_flag[b] = 1;
        }
        __syncthreads();
    } else {
        if (tid == 0) {
            while (g_flag[b] == 0) __nanosleep(64);
            shv = *((volatile float*)&g_val[b]);
            she = *((volatile int*)&g_idx[b]);
        }
        __syncthreads();
    }
    const float val = shv;
    const int   e   = she;

    // ---- Phase 2: fp16 GEMM. 8 warps: wf=warp>>1 (16 f rows), wn=warp&1 (64 hw) ----
    const int wf = warp >> 1;
    const int wn = warp & 1;
    const uint32_t sxb = smem_u32(sX);

    uint32_t af[4][4];
    {
        const float* Wb = expert_w + (size_t)e * 4096;
        int r0 = wf * 16 + (lane >> 2);
        int kA = (lane & 3) * 2;
        #pragma unroll
        for (int kt = 0; kt < 4; kt++) {
            int k0 = kt * 16 + kA;
            float2 w0 = *(const float2*)(Wb + r0 * 64 + k0);
            float2 w1 = *(const float2*)(Wb + (r0 + 8) * 64 + k0);
            float2 w2 = *(const float2*)(Wb + r0 * 64 + k0 + 8);
            float2 w3 = *(const float2*)(Wb + (r0 + 8) * 64 + k0 + 8);
            af[kt][0] = pack_f16x2(w0.x, w0.y);
            af[kt][1] = pack_f16x2(w1.x, w1.y);
            af[kt][2] = pack_f16x2(w2.x, w2.y);
            af[kt][3] = pack_f16x2(w3.x, w3.y);
        }
    }

    float acc[8][4];
    #pragma unroll
    for (int nt = 0; nt < 8; nt++)
        #pragma unroll
        for (int q = 0; q < 4; q++) acc[nt][q] = 0.f;

    const uint32_t krow = (uint32_t)(lane & 15);
    #pragma unroll
    for (int kt = 0; kt < 4; kt++) {
        uint32_t kbase = ((uint32_t)(kt * 16) + krow) * (XPITCH * 4u);
        #pragma unroll
        for (int nt = 0; nt < 8; nt++) {
            uint32_t noff = (uint32_t)(wn * 64 + nt * 8) * 2u;
            uint32_t bf[2];
            LDMATRIX_X2T(bf, sxb + kbase + noff);
            MMA_F16(acc[nt], af[kt], bf[0], bf[1]);
        }
    }

    // ---- epilogue: streaming stores ----
    float* outb = out + (size_t)b * CC * HWC + hw0;
    int f0 = wf * 16 + (lane >> 2);
    int cbase = wn * 64 + (lane & 3) * 2;
    #pragma unroll
    for (int nt = 0; nt < 8; nt++) {
        int cc = cbase + nt * 8;
        float2 v0 = make_float2(acc[nt][0] * val, acc[nt][1] * val);
        float2 v1 = make_float2(acc[nt][2] * val, acc[nt][3] * val);
        __stcs((float2*)(outb + (size_t)f0 * HWC + cc),       v0);
        __stcs((float2*)(outb + (size_t)(f0 + 8) * HWC + cc), v1);
    }
}

// ===========================================================================
extern "C" void kernel_launch(void* const* d_in, const int* in_sizes, int n_in,
                              void* d_out, int out_size) {
    const float* x = nullptr, *gate_w = nullptr, *gate_b = nullptr, *expert_w = nullptr;
    for (int i = 0; i < n_in; i++) {
        switch (in_sizes[i]) {
            case BB*CC*HH*WW: x        = (const float*)d_in[i]; break;  // 524288
            case EE*CC*3*3:   gate_w   = (const float*)d_in[i]; break;  // 4608
            case EE:          gate_b   = (const float*)d_in[i]; break;  // 8
            case EE*CC*CC:    expert_w = (const float*)d_in[i]; break;  // 32768
            default: break;
        }
    }
    float* out = (float*)d_out;
    const int main_elems = BB * CC * HWC;
    int write_ew = (out_size >= main_elems + BB * EE) ? 1 : 0;

    zero_kernel<<<36, 512>>>();
    fused_kernel<<<dim3(HWC / 128, BB), 256>>>(x, expert_w, gate_w, gate_b, out, write_ew);
}

// round 10
// speedup vs baseline: 1.1128x; 1.1128x over previous
#include <cuda_runtime.h>
#include <cuda_fp16.h>
#include <cstdint>

#define BB 32
#define CC 64
#define HH 64
#define WW 64
#define EE 8
#define HWC (HH*WW)

// Scratch (device globals: no allocation allowed)
__device__ float g_S[BB * 9 * CC];            // box sums [(b*9+k)*64+c], k=di*3+dj
__device__ uint2 g_x16[BB * CC * HWC / 4];    // fp16 copy of x, 4 halves per uint2

// ===========================================================================
// helpers
// ===========================================================================
__device__ __forceinline__ uint32_t smem_u32(const void* p) {
    uint32_t a;
    asm("{ .reg .u64 t; cvta.to.shared.u64 t, %1; cvt.u32.u64 %0, t; }" : "=r"(a) : "l"(p));
    return a;
}

__device__ __forceinline__ uint32_t pack_f16x2(float even, float odd) {
    __half2 h = __floats2half2_rn(even, odd);
    return *reinterpret_cast<uint32_t*>(&h);
}

#define LDMATRIX_X2T(R, addr) \
    asm volatile("ldmatrix.sync.aligned.m8n8.x2.trans.shared.b16 {%0,%1}, [%2];" \
        : "=r"((R)[0]), "=r"((R)[1]) : "r"(addr))

#define MMA_F16(D, A, B0, B1) \
    asm volatile("mma.sync.aligned.m16n8k16.row.col.f32.f16.f16.f32 " \
        "{%0,%1,%2,%3}, {%4,%5,%6,%7}, {%8,%9}, {%0,%1,%2,%3};" \
        : "+f"((D)[0]), "+f"((D)[1]), "+f"((D)[2]), "+f"((D)[3]) \
        : "r"((A)[0]), "r"((A)[1]), "r"((A)[2]), "r"((A)[3]), "r"(B0), "r"(B1))

// ===========================================================================
// Kernel A: box sums (R6-proven pattern) + fp16 conversion write.
// Block = one (b,c) image; 256 threads; thread loads float4 at i*256+tid.
// x read from DRAM exactly once per element. x16 written L2-cached (stcg).
// ===========================================================================
__global__ __launch_bounds__(256) void region_convert_kernel(const float* __restrict__ x) {
    const int tid = threadIdx.x;
    const float4* base = (const float4*)(x + (size_t)blockIdx.x * HWC);
    float4 v[4];
    #pragma unroll
    for (int i = 0; i < 4; i++) v[i] = base[i * 256 + tid];

    // ---- fp16 conversion write (L2-resident for kernel B) ----
    uint2* xout = g_x16 + (size_t)blockIdx.x * (HWC / 4);
    #pragma unroll
    for (int i = 0; i < 4; i++) {
        uint2 w;
        w.x = pack_f16x2(v[i].x, v[i].y);
        w.y = pack_f16x2(v[i].z, v[i].w);
        __stcg(xout + i * 256 + tid, w);
    }

    const int g  = tid >> 4;   // 0..15 ; rows touched = i*16 + g
    const int c4 = tid & 15;   // float4 within row

    __shared__ float sRow[4][16];  // partial sums of edge rows 0,1,62,63
    __shared__ float sRE[4][4];    // edge row elems: x[r][0],[1],[62],[63]
    __shared__ float sCol[4][16];  // per-g partials of cols 0,1,62,63
    __shared__ float sG[8];        // per-warp grand totals

    float ps[4], gsum = 0.f;
    #pragma unroll
    for (int i = 0; i < 4; i++) {
        ps[i] = (v[i].x + v[i].y) + (v[i].z + v[i].w);
        gsum += ps[i];
    }
    // edge rows: 0=(i0,g0), 1=(i0,g1), 62=(i3,g14), 63=(i3,g15)
    if (g == 0)  sRow[0][c4] = ps[0];
    if (g == 1)  sRow[1][c4] = ps[0];
    if (g == 14) sRow[2][c4] = ps[3];
    if (g == 15) sRow[3][c4] = ps[3];
    if (c4 == 0) {
        float cl0 = (v[0].x + v[1].x) + (v[2].x + v[3].x);
        float cl1 = (v[0].y + v[1].y) + (v[2].y + v[3].y);
        sCol[0][g] = cl0; sCol[1][g] = cl1;
        if (g == 0)  { sRE[0][0] = v[0].x; sRE[0][1] = v[0].y; }
        if (g == 1)  { sRE[1][0] = v[0].x; sRE[1][1] = v[0].y; }
        if (g == 14) { sRE[2][0] = v[3].x; sRE[2][1] = v[3].y; }
        if (g == 15) { sRE[3][0] = v[3].x; sRE[3][1] = v[3].y; }
    }
    if (c4 == 15) {
        float cr0 = (v[0].z + v[1].z) + (v[2].z + v[3].z);
        float cr1 = (v[0].w + v[1].w) + (v[2].w + v[3].w);
        sCol[2][g] = cr0; sCol[3][g] = cr1;
        if (g == 0)  { sRE[0][2] = v[0].z; sRE[0][3] = v[0].w; }
        if (g == 1)  { sRE[1][2] = v[0].z; sRE[1][3] = v[0].w; }
        if (g == 14) { sRE[2][2] = v[3].z; sRE[2][3] = v[3].w; }
        if (g == 15) { sRE[3][2] = v[3].z; sRE[3][3] = v[3].w; }
    }
    #pragma unroll
    for (int o = 16; o; o >>= 1) gsum += __shfl_xor_sync(0xffffffffu, gsum, o);
    if ((tid & 31) == 0) sG[tid >> 5] = gsum;
    __syncthreads();

    if (tid < 9) {
        int di = tid / 3, dj = tid - di * 3;
        float G = 0.f;
        #pragma unroll
        for (int j = 0; j < 8; j++) G += sG[j];
        float c0 = 0.f, c1 = 0.f, c62 = 0.f, c63 = 0.f;
        #pragma unroll
        for (int j = 0; j < 16; j++) {
            c0 += sCol[0][j]; c1 += sCol[1][j]; c62 += sCol[2][j]; c63 += sCol[3][j];
        }
        float colc = (dj == 0) ? (c62 + c63) : (dj == 1) ? (c0 + c63) : (c0 + c1);
        float T = G - colc;                 // sum of cv_dj over all 64 rows
        float rw[4];
        #pragma unroll
        for (int er = 0; er < 4; er++) {
            float s = 0.f;
            #pragma unroll
            for (int j = 0; j < 16; j++) s += sRow[er][j];
            float ec = (dj == 0) ? (sRE[er][2] + sRE[er][3])
                     : (dj == 1) ? (sRE[er][0] + sRE[er][3])
                                 : (sRE[er][0] + sRE[er][1]);
            rw[er] = s - ec;                // cv_dj of that edge row
        }
        float sub = (di == 0) ? (rw[2] + rw[3])
                  : (di == 1) ? (rw[0] + rw[3])
                              : (rw[0] + rw[1]);
        int b = blockIdx.x >> 6, c = blockIdx.x & 63;
        g_S[(b * 9 + tid) * CC + c] = T - sub;
    }
}

// ===========================================================================
// Kernel B: per-block redundant gate (L2-hot, no sync) + fp16 mma.sync GEMM
// reading the L2-resident x16. Grid (chunk=0..31, b=0..31); 256 threads.
// Warp wf=warp>>1 covers 16 f rows; wn=warp&1 covers 64 hw cols.
// ===========================================================================
#define XPITCH 68u   // words per X row (64 data words + 4 pad)

__global__ __launch_bounds__(256) void gate_gemm_kernel(const float* __restrict__ expert_w,
                                                        const float* __restrict__ gate_w,
                                                        const float* __restrict__ gate_b,
                                                        float* __restrict__ out,
                                                        int write_ew) {
    __shared__ uint32_t sX[64 * XPITCH];
    __shared__ float sGat[8];
    __shared__ float shv;
    __shared__ int   she;

    const int tid   = threadIdx.x;
    const int warp  = tid >> 5, lane = tid & 31;
    const int chunk = blockIdx.x;
    const int b     = blockIdx.y;
    const int hw0   = chunk * 128;

    // ---- stage x16 tile from L2 into smem (batched, coalesced) ----
    const uint2* xs = g_x16 + ((size_t)b * CC * HWC + hw0) / 4;
    uint2 xv[8];
    #pragma unroll
    for (int i = 0; i < 8; i++) {
        int p = tid + i * 256;              // uint2 index 0..2047
        int c = p >> 5, q = p & 31;         // 32 uint2 per 128-half row
        xv[i] = __ldcg(xs + (size_t)c * (HWC / 4) + q);
    }
    #pragma unroll
    for (int i = 0; i < 8; i++) {
        int p = tid + i * 256;
        int c = p >> 5, q = p & 31;
        *(uint2*)(sX + c * XPITCH + q * 2) = xv[i];
    }

    // ---- gate (redundant per block; all inputs L2-hot) ----
    float a0 = 0.f;
    for (int idx = lane; idx < 576; idx += 32) {
        int c = idx / 9, k = idx - c * 9;
        a0 += gate_w[warp * 576 + idx] * g_S[(b * 9 + k) * CC + c];
    }
    #pragma unroll
    for (int o = 16; o; o >>= 1) a0 += __shfl_down_sync(0xffffffffu, a0, o);
    if (lane == 0) sGat[warp] = a0 + gate_b[warp] * 3844.0f;   // 62*62 positions
    __syncthreads();

    if (tid == 0) {
        float m = sGat[0]; int mi = 0;
        #pragma unroll
        for (int e2 = 1; e2 < 8; e2++) { if (sGat[e2] > m) { m = sGat[e2]; mi = e2; } }
        float s = 0.f;
        #pragma unroll
        for (int e2 = 0; e2 < 8; e2++) s += expf(sGat[e2] - m);
        float v_ = 1.0f / s;
        shv = v_; she = mi;
        if (write_ew && chunk == 0) {
            float* ew = out + BB * CC * HWC + b * 8;
            #pragma unroll
            for (int e2 = 0; e2 < 8; e2++) ew[e2] = (e2 == mi) ? v_ : 0.0f;
        }
    }
    __syncthreads();
    const float val = shv;
    const int   e   = she;

    // ---- A fragments (fp16 W) straight from gmem (L2-hot, 16KB) ----
    const int wf = warp >> 1;   // 0..3 : 16 f rows each
    const int wn = warp & 1;    // 0..1 : 64 hw cols each
    uint32_t af[4][4];
    {
        const float* Wb = expert_w + (size_t)e * 4096;
        int r0 = wf * 16 + (lane >> 2);
        int kA = (lane & 3) * 2;
        #pragma unroll
        for (int kt = 0; kt < 4; kt++) {
            int k0 = kt * 16 + kA;
            float2 w0 = *(const float2*)(Wb + r0 * 64 + k0);
            float2 w1 = *(const float2*)(Wb + (r0 + 8) * 64 + k0);
            float2 w2 = *(const float2*)(Wb + r0 * 64 + k0 + 8);
            float2 w3 = *(const float2*)(Wb + (r0 + 8) * 64 + k0 + 8);
            af[kt][0] = pack_f16x2(w0.x, w0.y);
            af[kt][1] = pack_f16x2(w1.x, w1.y);
            af[kt][2] = pack_f16x2(w2.x, w2.y);
            af[kt][3] = pack_f16x2(w3.x, w3.y);
        }
    }

    float acc[8][4];
    #pragma unroll
    for (int nt = 0; nt < 8; nt++)
        #pragma unroll
        for (int q = 0; q < 4; q++) acc[nt][q] = 0.f;

    const uint32_t sxb = smem_u32(sX);
    const uint32_t krow = (uint32_t)(lane & 15);
    #pragma unroll
    for (int kt = 0; kt < 4; kt++) {
        uint32_t kbase = ((uint32_t)(kt * 16) + krow) * (XPITCH * 4u);
        #pragma unroll
        for (int nt = 0; nt < 8; nt++) {
            uint32_t noff = (uint32_t)(wn * 64 + nt * 8) * 2u;
            uint32_t bf[2];
            LDMATRIX_X2T(bf, sxb + kbase + noff);
            MMA_F16(acc[nt], af[kt], bf[0], bf[1]);
        }
    }

    // ---- epilogue: streaming stores ----
    float* outb = out + (size_t)b * CC * HWC + hw0;
    int f0 = wf * 16 + (lane >> 2);
    int cbase = wn * 64 + (lane & 3) * 2;
    #pragma unroll
    for (int nt = 0; nt < 8; nt++) {
        int cc = cbase + nt * 8;
        float2 v0 = make_float2(acc[nt][0] * val, acc[nt][1] * val);
        float2 v1 = make_float2(acc[nt][2] * val, acc[nt][3] * val);
        __stcs((float2*)(outb + (size_t)f0 * HWC + cc),       v0);
        __stcs((float2*)(outb + (size_t)(f0 + 8) * HWC + cc), v1);
    }
}

// ===========================================================================
extern "C" void kernel_launch(void* const* d_in, const int* in_sizes, int n_in,
                              void* d_out, int out_size) {
    const float* x = nullptr, *gate_w = nullptr, *gate_b = nullptr, *expert_w = nullptr;
    for (int i = 0; i < n_in; i++) {
        switch (in_sizes[i]) {
            case BB*CC*HH*WW: x        = (const float*)d_in[i]; break;  // 524288
            case EE*CC*3*3:   gate_w   = (const float*)d_in[i]; break;  // 4608
            case EE:          gate_b   = (const float*)d_in[i]; break;  // 8
            case EE*CC*CC:    expert_w = (const float*)d_in[i]; break;  // 32768
            default: break;
        }
    }
    float* out = (float*)d_out;
    const int main_elems = BB * CC * HWC;
    int write_ew = (out_size >= main_elems + BB * EE) ? 1 : 0;

    region_convert_kernel<<<BB * CC, 256>>>(x);
    gate_gemm_kernel<<<dim3(HWC / 128, BB), 256>>>(expert_w, gate_w, gate_b, out, write_ew);
}

// round 11
// speedup vs baseline: 1.1829x; 1.0630x over previous
#include <cuda_runtime.h>
#include <cuda_fp16.h>
#include <cstdint>

#define BB 32
#define CC 64
#define HH 64
#define WW 64
#define EE 8
#define HWC (HH*WW)

// Scratch (device globals: no allocation allowed)
__device__ float g_S[BB * 9 * CC];            // box sums [(b*9+k)*64+c], k=di*3+dj
__device__ float g_val[BB];
__device__ int   g_idx[BB];
__device__ uint2 g_x16[BB * CC * HWC / 4];    // fp16 copy of x, 4 halves per uint2

// ===========================================================================
// helpers
// ===========================================================================
__device__ __forceinline__ uint32_t smem_u32(const void* p) {
    uint32_t a;
    asm("{ .reg .u64 t; cvta.to.shared.u64 t, %1; cvt.u32.u64 %0, t; }" : "=r"(a) : "l"(p));
    return a;
}

__device__ __forceinline__ uint32_t pack_f16x2(float even, float odd) {
    __half2 h = __floats2half2_rn(even, odd);
    return *reinterpret_cast<uint32_t*>(&h);
}

#define LDMATRIX_X2T(R, addr) \
    asm volatile("ldmatrix.sync.aligned.m8n8.x2.trans.shared.b16 {%0,%1}, [%2];" \
        : "=r"((R)[0]), "=r"((R)[1]) : "r"(addr))

#define MMA_F16(D, A, B0, B1) \
    asm volatile("mma.sync.aligned.m16n8k16.row.col.f32.f16.f16.f32 " \
        "{%0,%1,%2,%3}, {%4,%5,%6,%7}, {%8,%9}, {%0,%1,%2,%3};" \
        : "+f"((D)[0]), "+f"((D)[1]), "+f"((D)[2]), "+f"((D)[3]) \
        : "r"((A)[0]), "r"((A)[1]), "r"((A)[2]), "r"((A)[3]), "r"(B0), "r"(B1))

// ===========================================================================
// Kernel A: box sums + fp16 conversion write (measured ~7.2us in R10).
// Block = one (b,c) image; 256 threads; thread loads float4 at i*256+tid.
// x read from DRAM exactly once per element. x16 written L2-cached (stcg).
// ===========================================================================
__global__ __launch_bounds__(256) void region_convert_kernel(const float* __restrict__ x) {
    const int tid = threadIdx.x;
    const float4* base = (const float4*)(x + (size_t)blockIdx.x * HWC);
    float4 v[4];
    #pragma unroll
    for (int i = 0; i < 4; i++) v[i] = base[i * 256 + tid];

    // ---- fp16 conversion write (L2-resident for kernel B) ----
    uint2* xout = g_x16 + (size_t)blockIdx.x * (HWC / 4);
    #pragma unroll
    for (int i = 0; i < 4; i++) {
        uint2 w;
        w.x = pack_f16x2(v[i].x, v[i].y);
        w.y = pack_f16x2(v[i].z, v[i].w);
        __stcg(xout + i * 256 + tid, w);
    }

    const int g  = tid >> 4;   // 0..15 ; rows touched = i*16 + g
    const int c4 = tid & 15;   // float4 within row

    __shared__ float sRow[4][16];  // partial sums of edge rows 0,1,62,63
    __shared__ float sRE[4][4];    // edge row elems: x[r][0],[1],[62],[63]
    __shared__ float sCol[4][16];  // per-g partials of cols 0,1,62,63
    __shared__ float sG[8];        // per-warp grand totals

    float ps[4], gsum = 0.f;
    #pragma unroll
    for (int i = 0; i < 4; i++) {
        ps[i] = (v[i].x + v[i].y) + (v[i].z + v[i].w);
        gsum += ps[i];
    }
    // edge rows: 0=(i0,g0), 1=(i0,g1), 62=(i3,g14), 63=(i3,g15)
    if (g == 0)  sRow[0][c4] = ps[0];
    if (g == 1)  sRow[1][c4] = ps[0];
    if (g == 14) sRow[2][c4] = ps[3];
    if (g == 15) sRow[3][c4] = ps[3];
    if (c4 == 0) {
        float cl0 = (v[0].x + v[1].x) + (v[2].x + v[3].x);
        float cl1 = (v[0].y + v[1].y) + (v[2].y + v[3].y);
        sCol[0][g] = cl0; sCol[1][g] = cl1;
        if (g == 0)  { sRE[0][0] = v[0].x; sRE[0][1] = v[0].y; }
        if (g == 1)  { sRE[1][0] = v[0].x; sRE[1][1] = v[0].y; }
        if (g == 14) { sRE[2][0] = v[3].x; sRE[2][1] = v[3].y; }
        if (g == 15) { sRE[3][0] = v[3].x; sRE[3][1] = v[3].y; }
    }
    if (c4 == 15) {
        float cr0 = (v[0].z + v[1].z) + (v[2].z + v[3].z);
        float cr1 = (v[0].w + v[1].w) + (v[2].w + v[3].w);
        sCol[2][g] = cr0; sCol[3][g] = cr1;
        if (g == 0)  { sRE[0][2] = v[0].z; sRE[0][3] = v[0].w; }
        if (g == 1)  { sRE[1][2] = v[0].z; sRE[1][3] = v[0].w; }
        if (g == 14) { sRE[2][2] = v[3].z; sRE[2][3] = v[3].w; }
        if (g == 15) { sRE[3][2] = v[3].z; sRE[3][3] = v[3].w; }
    }
    #pragma unroll
    for (int o = 16; o; o >>= 1) gsum += __shfl_xor_sync(0xffffffffu, gsum, o);
    if ((tid & 31) == 0) sG[tid >> 5] = gsum;
    __syncthreads();

    if (tid < 9) {
        int di = tid / 3, dj = tid - di * 3;
        float G = 0.f;
        #pragma unroll
        for (int j = 0; j < 8; j++) G += sG[j];
        float c0 = 0.f, c1 = 0.f, c62 = 0.f, c63 = 0.f;
        #pragma unroll
        for (int j = 0; j < 16; j++) {
            c0 += sCol[0][j]; c1 += sCol[1][j]; c62 += sCol[2][j]; c63 += sCol[3][j];
        }
        float colc = (dj == 0) ? (c62 + c63) : (dj == 1) ? (c0 + c63) : (c0 + c1);
        float T = G - colc;                 // sum of cv_dj over all 64 rows
        float rw[4];
        #pragma unroll
        for (int er = 0; er < 4; er++) {
            float s = 0.f;
            #pragma unroll
            for (int j = 0; j < 16; j++) s += sRow[er][j];
            float ec = (dj == 0) ? (sRE[er][2] + sRE[er][3])
                     : (dj == 1) ? (sRE[er][0] + sRE[er][3])
                                 : (sRE[er][0] + sRE[er][1]);
            rw[er] = s - ec;                // cv_dj of that edge row
        }
        float sub = (di == 0) ? (rw[2] + rw[3])
                  : (di == 1) ? (rw[0] + rw[3])
                              : (rw[0] + rw[1]);
        int b = blockIdx.x >> 6, c = blockIdx.x & 63;
        g_S[(b * 9 + tid) * CC + c] = T - sub;
    }
}

// ===========================================================================
// Kernel G: gate (32 blocks; smem-staged g_S so the k*64+c scatter hits smem).
// ===========================================================================
__global__ __launch_bounds__(256) void gate_kernel(const float* __restrict__ gate_w,
                                                   const float* __restrict__ gate_b,
                                                   float* __restrict__ ew_out,
                                                   int write_ew) {
    int b = blockIdx.x;
    int tid = threadIdx.x;
    __shared__ float Ssh[9 * 64];
    __shared__ float gat[8];

    for (int i = tid; i < 576; i += 256) Ssh[i] = g_S[b*576 + i];   // coalesced
    __syncthreads();

    int warp = tid >> 5, lane = tid & 31;  // warp = expert index
    float acc = 0.f;
    for (int idx = lane; idx < 576; idx += 32) {
        int c = idx / 9;
        int k = idx - c * 9;
        acc += gate_w[warp * 576 + idx] * Ssh[k * 64 + c];
    }
    #pragma unroll
    for (int o = 16; o; o >>= 1) acc += __shfl_down_sync(0xffffffffu, acc, o);
    if (lane == 0) gat[warp] = acc + gate_b[warp] * 3844.0f;  // 62*62 positions
    __syncthreads();

    if (tid == 0) {
        float m = gat[0]; int mi = 0;
        #pragma unroll
        for (int e = 1; e < 8; e++) { if (gat[e] > m) { m = gat[e]; mi = e; } }
        float s = 0.f;
        #pragma unroll
        for (int e = 0; e < 8; e++) s += expf(gat[e] - m);
        g_val[b] = 1.0f / s;
        g_idx[b] = mi;
    }
    __syncthreads();
    if (write_ew && tid < 8) {
        ew_out[b * 8 + tid] = (tid == g_idx[b]) ? g_val[b] : 0.0f;
    }
}

// ===========================================================================
// Kernel B: fp16 mma.sync GEMM reading L2-resident x16. No gate work.
// Grid (chunk=0..31, b=0..31); 256 threads; warp tile 16f x 64hw.
// ===========================================================================
#define XPITCH 68u   // words per X row (64 data words + 4 pad)

__global__ __launch_bounds__(256) void gemm_kernel(const float* __restrict__ expert_w,
                                                   float* __restrict__ out) {
    __shared__ uint32_t sX[64 * XPITCH];
    __shared__ float shv;
    __shared__ int   she;

    const int tid   = threadIdx.x;
    const int warp  = tid >> 5, lane = tid & 31;
    const int chunk = blockIdx.x;
    const int b     = blockIdx.y;
    const int hw0   = chunk * 128;

    if (tid == 0) { shv = g_val[b]; she = g_idx[b]; }

    // ---- stage x16 tile from L2 into smem (batched, coalesced) ----
    const uint2* xs = g_x16 + ((size_t)b * CC * HWC + hw0) / 4;
    uint2 xv[8];
    #pragma unroll
    for (int i = 0; i < 8; i++) {
        int p = tid + i * 256;              // uint2 index 0..2047
        int c = p >> 5, q = p & 31;         // 32 uint2 per 128-half row
        xv[i] = __ldcg(xs + (size_t)c * (HWC / 4) + q);
    }
    #pragma unroll
    for (int i = 0; i < 8; i++) {
        int p = tid + i * 256;
        int c = p >> 5, q = p & 31;
        *(uint2*)(sX + c * XPITCH + q * 2) = xv[i];
    }
    __syncthreads();
    const float val = shv;
    const int   e   = she;

    // ---- A fragments (fp16 W) straight from gmem (L2-hot, 16KB) ----
    const int wf = warp >> 1;   // 0..3 : 16 f rows each
    const int wn = warp & 1;    // 0..1 : 64 hw cols each
    uint32_t af[4][4];
    {
        const float* Wb = expert_w + (size_t)e * 4096;
        int r0 = wf * 16 + (lane >> 2);
        int kA = (lane & 3) * 2;
        #pragma unroll
        for (int kt = 0; kt < 4; kt++) {
            int k0 = kt * 16 + kA;
            float2 w0 = *(const float2*)(Wb + r0 * 64 + k0);
            float2 w1 = *(const float2*)(Wb + (r0 + 8) * 64 + k0);
            float2 w2 = *(const float2*)(Wb + r0 * 64 + k0 + 8);
            float2 w3 = *(const float2*)(Wb + (r0 + 8) * 64 + k0 + 8);
            af[kt][0] = pack_f16x2(w0.x, w0.y);
            af[kt][1] = pack_f16x2(w1.x, w1.y);
            af[kt][2] = pack_f16x2(w2.x, w2.y);
            af[kt][3] = pack_f16x2(w3.x, w3.y);
        }
    }

    float acc[8][4];
    #pragma unroll
    for (int nt = 0; nt < 8; nt++)
        #pragma unroll
        for (int q = 0; q < 4; q++) acc[nt][q] = 0.f;

    const uint32_t sxb = smem_u32(sX);
    const uint32_t krow = (uint32_t)(lane & 15);
    #pragma unroll
    for (int kt = 0; kt < 4; kt++) {
        uint32_t kbase = ((uint32_t)(kt * 16) + krow) * (XPITCH * 4u);
        #pragma unroll
        for (int nt = 0; nt < 8; nt++) {
            uint32_t noff = (uint32_t)(wn * 64 + nt * 8) * 2u;
            uint32_t bf[2];
            LDMATRIX_X2T(bf, sxb + kbase + noff);
            MMA_F16(acc[nt], af[kt], bf[0], bf[1]);
        }
    }

    // ---- epilogue: streaming stores ----
    float* outb = out + (size_t)b * CC * HWC + hw0;
    int f0 = wf * 16 + (lane >> 2);
    int cbase = wn * 64 + (lane & 3) * 2;
    #pragma unroll
    for (int nt = 0; nt < 8; nt++) {
        int cc = cbase + nt * 8;
        float2 v0 = make_float2(acc[nt][0] * val, acc[nt][1] * val);
        float2 v1 = make_float2(acc[nt][2] * val, acc[nt][3] * val);
        __stcs((float2*)(outb + (size_t)f0 * HWC + cc),       v0);
        __stcs((float2*)(outb + (size_t)(f0 + 8) * HWC + cc), v1);
    }
}

// ===========================================================================
extern "C" void kernel_launch(void* const* d_in, const int* in_sizes, int n_in,
                              void* d_out, int out_size) {
    const float* x = nullptr, *gate_w = nullptr, *gate_b = nullptr, *expert_w = nullptr;
    for (int i = 0; i < n_in; i++) {
        switch (in_sizes[i]) {
            case BB*CC*HH*WW: x        = (const float*)d_in[i]; break;  // 524288
            case EE*CC*3*3:   gate_w   = (const float*)d_in[i]; break;  // 4608
            case EE:          gate_b   = (const float*)d_in[i]; break;  // 8
            case EE*CC*CC:    expert_w = (const float*)d_in[i]; break;  // 32768
            default: break;
        }
    }
    float* out = (float*)d_out;
    const int main_elems = BB * CC * HWC;
    int write_ew = (out_size >= main_elems + BB * EE) ? 1 : 0;

    region_convert_kernel<<<BB * CC, 256>>>(x);
    gate_kernel<<<BB, 256>>>(gate_w, gate_b, out + main_elems, write_ew);
    gemm_kernel<<<dim3(HWC / 128, BB), 256>>>(expert_w, out);
}

// round 12
// speedup vs baseline: 1.1951x; 1.0103x over previous
#include <cuda_runtime.h>
#include <cuda_fp16.h>
#include <cstdint>

#define BB 32
#define CC 64
#define HH 64
#define WW 64
#define EE 8
#define HWC (HH*WW)

// Scratch (device globals: no allocation allowed)
__device__ float        g_S[BB * 9 * CC];   // box sums [(b*9+k)*64+c]
__device__ int          g_cnt[BB];
__device__ volatile int g_flag[BB];
__device__ volatile float g_val[BB];
__device__ volatile int   g_idx[BB];
__device__ uint2        g_x16[BB * CC * HWC / 4];   // fp16 x, 4 halves/uint2

// ===========================================================================
// helpers
// ===========================================================================
__device__ __forceinline__ uint32_t smem_u32(const void* p) {
    uint32_t a;
    asm("{ .reg .u64 t; cvta.to.shared.u64 t, %1; cvt.u32.u64 %0, t; }" : "=r"(a) : "l"(p));
    return a;
}

__device__ __forceinline__ uint32_t pack_f16x2(float even, float odd) {
    __half2 h = __floats2half2_rn(even, odd);
    return *reinterpret_cast<uint32_t*>(&h);
}

#define LDMATRIX_X2T(R, addr) \
    asm volatile("ldmatrix.sync.aligned.m8n8.x2.trans.shared.b16 {%0,%1}, [%2];" \
        : "=r"((R)[0]), "=r"((R)[1]) : "r"(addr))

#define MMA_F16(D, A, B0, B1) \
    asm volatile("mma.sync.aligned.m16n8k16.row.col.f32.f16.f16.f32 " \
        "{%0,%1,%2,%3}, {%4,%5,%6,%7}, {%8,%9}, {%0,%1,%2,%3};" \
        : "+f"((D)[0]), "+f"((D)[1]), "+f"((D)[2]), "+f"((D)[3]) \
        : "r"((A)[0]), "r"((A)[1]), "r"((A)[2]), "r"((A)[3]), "r"(B0), "r"(B1))

// ===========================================================================
// Kernel 0: reset counters/flags (tiny; g_S is written directly, no zeroing)
// ===========================================================================
__global__ void zero_kernel() {
    int i = threadIdx.x;
    if (i < BB) { g_cnt[i] = 0; g_flag[i] = 0; }
}

// ===========================================================================
// Pipe kernel: 2048 blocks, 256 threads.
//  bid < 1024 : A-role. b=bid>>5, channels 2*(bid&31), +1.
//    region stats + fp16 convert (x read ONCE); direct g_S writes;
//    last block of batch computes gate inline, sets flag[b].
//  bid >= 1024: B-role. b=(bid-1024)>>5, chunk=(bid-1024)&31.
//    spin on flag[b] (set ~1024 bids earlier -> ~no waiting), then
//    fp16 mma.sync GEMM reading L2-hot g_x16, streaming stores to out.
//  Overlap: B write-stream runs concurrently with A read-stream.
// ===========================================================================
#define XPITCH 68u   // words per X row (64 data words + 4 pad)

__global__ __launch_bounds__(256) void pipe_kernel(const float* __restrict__ x,
                                                   const float* __restrict__ expert_w,
                                                   const float* __restrict__ gate_w,
                                                   const float* __restrict__ gate_b,
                                                   float* __restrict__ out,
                                                   int write_ew) {
    __shared__ uint32_t sX[64 * XPITCH];     // B-role tile / unused by A
    __shared__ float sRow[2][4][16];
    __shared__ float sRE[2][4][4];
    __shared__ float sCol[2][4][16];
    __shared__ float sG[2][8];
    __shared__ float Ssh[9 * 64];
    __shared__ float gat[8];
    __shared__ float shv;
    __shared__ int   she, shLast;

    const int tid  = threadIdx.x;
    const int warp = tid >> 5, lane = tid & 31;
    const int bid  = blockIdx.x;

    if (bid < 1024) {
        // ================= A-role =================
        const int b     = bid >> 5;
        const int cpair = bid & 31;
        const int c0    = cpair * 2;

        const float4* base0 = (const float4*)(x + ((size_t)b * CC + c0) * HWC);
        const float4* base1 = (const float4*)(x + ((size_t)b * CC + c0 + 1) * HWC);
        float4 va[4], vb4[4];
        #pragma unroll
        for (int i = 0; i < 4; i++) va[i]  = base0[i * 256 + tid];
        #pragma unroll
        for (int i = 0; i < 4; i++) vb4[i] = base1[i * 256 + tid];

        // fp16 conversion writes (L2-resident for B-role)
        {
            uint2* xo0 = g_x16 + ((size_t)b * CC + c0) * (HWC / 4);
            uint2* xo1 = xo0 + (HWC / 4);
            #pragma unroll
            for (int i = 0; i < 4; i++) {
                uint2 w0, w1;
                w0.x = pack_f16x2(va[i].x,  va[i].y);  w0.y = pack_f16x2(va[i].z,  va[i].w);
                w1.x = pack_f16x2(vb4[i].x, vb4[i].y); w1.y = pack_f16x2(vb4[i].z, vb4[i].w);
                __stcg(xo0 + i * 256 + tid, w0);
                __stcg(xo1 + i * 256 + tid, w1);
            }
        }

        const int g  = tid >> 4;   // rows touched = i*16 + g
        const int c4 = tid & 15;

        #pragma unroll
        for (int m = 0; m < 2; m++) {
            const float4* v = m ? vb4 : va;
            float ps[4], gsum = 0.f;
            #pragma unroll
            for (int i = 0; i < 4; i++) {
                ps[i] = (v[i].x + v[i].y) + (v[i].z + v[i].w);
                gsum += ps[i];
            }
            if (g == 0)  sRow[m][0][c4] = ps[0];
            if (g == 1)  sRow[m][1][c4] = ps[0];
            if (g == 14) sRow[m][2][c4] = ps[3];
            if (g == 15) sRow[m][3][c4] = ps[3];
            if (c4 == 0) {
                sCol[m][0][g] = (v[0].x + v[1].x) + (v[2].x + v[3].x);
                sCol[m][1][g] = (v[0].y + v[1].y) + (v[2].y + v[3].y);
                if (g == 0)  { sRE[m][0][0] = v[0].x; sRE[m][0][1] = v[0].y; }
                if (g == 1)  { sRE[m][1][0] = v[0].x; sRE[m][1][1] = v[0].y; }
                if (g == 14) { sRE[m][2][0] = v[3].x; sRE[m][2][1] = v[3].y; }
                if (g == 15) { sRE[m][3][0] = v[3].x; sRE[m][3][1] = v[3].y; }
            }
            if (c4 == 15) {
                sCol[m][2][g] = (v[0].z + v[1].z) + (v[2].z + v[3].z);
                sCol[m][3][g] = (v[0].w + v[1].w) + (v[2].w + v[3].w);
                if (g == 0)  { sRE[m][0][2] = v[0].z; sRE[m][0][3] = v[0].w; }
                if (g == 1)  { sRE[m][1][2] = v[0].z; sRE[m][1][3] = v[0].w; }
                if (g == 14) { sRE[m][2][2] = v[3].z; sRE[m][2][3] = v[3].w; }
                if (g == 15) { sRE[m][3][2] = v[3].z; sRE[m][3][3] = v[3].w; }
            }
            #pragma unroll
            for (int o = 16; o; o >>= 1) gsum += __shfl_xor_sync(0xffffffffu, gsum, o);
            if (lane == 0) sG[m][warp] = gsum;
        }
        __syncthreads();

        if (tid < 18) {
            int m = tid / 9, k = tid - m * 9;
            int di = k / 3, dj = k - di * 3;
            float G = 0.f;
            #pragma unroll
            for (int j = 0; j < 8; j++) G += sG[m][j];
            float cc0 = 0.f, cc1 = 0.f, cc62 = 0.f, cc63 = 0.f;
            #pragma unroll
            for (int j = 0; j < 16; j++) {
                cc0 += sCol[m][0][j]; cc1 += sCol[m][1][j];
                cc62 += sCol[m][2][j]; cc63 += sCol[m][3][j];
            }
            float colc = (dj == 0) ? (cc62 + cc63) : (dj == 1) ? (cc0 + cc63) : (cc0 + cc1);
            float T = G - colc;
            float rw[4];
            #pragma unroll
            for (int er = 0; er < 4; er++) {
                float s = 0.f;
                #pragma unroll
                for (int j = 0; j < 16; j++) s += sRow[m][er][j];
                float ec = (dj == 0) ? (sRE[m][er][2] + sRE[m][er][3])
                         : (dj == 1) ? (sRE[m][er][0] + sRE[m][er][3])
                                     : (sRE[m][er][0] + sRE[m][er][1]);
                rw[er] = s - ec;
            }
            float sub = (di == 0) ? (rw[2] + rw[3])
                      : (di == 1) ? (rw[0] + rw[3])
                                  : (rw[0] + rw[1]);
            g_S[(b * 9 + k) * CC + (c0 + m)] = T - sub;
        }
        __syncthreads();

        if (tid == 0) {
            __threadfence();
            int old = atomicAdd(&g_cnt[b], 1);
            shLast = (old == 31);
        }
        __syncthreads();
        if (!shLast) return;

        // ---- gate (last block of this batch; g_S complete) ----
        __threadfence();
        for (int i = tid; i < 576; i += 256) Ssh[i] = g_S[b * 576 + i];
        __syncthreads();
        float acc = 0.f;
        for (int idx = lane; idx < 576; idx += 32) {
            int c = idx / 9;
            int k = idx - c * 9;
            acc += gate_w[warp * 576 + idx] * Ssh[k * 64 + c];
        }
        #pragma unroll
        for (int o = 16; o; o >>= 1) acc += __shfl_down_sync(0xffffffffu, acc, o);
        if (lane == 0) gat[warp] = acc + gate_b[warp] * 3844.0f;
        __syncthreads();
        if (tid == 0) {
            float mm = gat[0]; int mi = 0;
            #pragma unroll
            for (int e2 = 1; e2 < 8; e2++) { if (gat[e2] > mm) { mm = gat[e2]; mi = e2; } }
            float s = 0.f;
            #pragma unroll
            for (int e2 = 0; e2 < 8; e2++) s += expf(gat[e2] - mm);
            float v_ = 1.0f / s;
            g_val[b] = v_;
            g_idx[b] = mi;
            if (write_ew) {
                float* ew = out + BB * CC * HWC + b * 8;
                #pragma unroll
                for (int e2 = 0; e2 < 8; e2++) ew[e2] = (e2 == mi) ? v_ : 0.0f;
            }
            __threadfence();
            g_flag[b] = 1;
        }
        return;
    }

    // ================= B-role =================
    const int q     = bid - 1024;
    const int b     = q >> 5;
    const int chunk = q & 31;
    const int hw0   = chunk * 128;

    if (tid == 0) {
        while (g_flag[b] == 0) __nanosleep(128);
        __threadfence();
        shv = g_val[b];
        she = g_idx[b];
    }

    // ---- stage x16 tile from L2 into smem ----
    const uint2* xs = g_x16 + ((size_t)b * CC * HWC + hw0) / 4;
    uint2 xv[8];
    #pragma unroll
    for (int i = 0; i < 8; i++) {
        int p = tid + i * 256;
        int c = p >> 5, qq = p & 31;
        xv[i] = __ldcg(xs + (size_t)c * (HWC / 4) + qq);
    }
    #pragma unroll
    for (int i = 0; i < 8; i++) {
        int p = tid + i * 256;
        int c = p >> 5, qq = p & 31;
        *(uint2*)(sX + c * XPITCH + qq * 2) = xv[i];
    }
    __syncthreads();
    const float val = shv;
    const int   e   = she;

    // ---- A fragments (fp16 W) from L2-hot gmem ----
    const int wf = warp >> 1;   // 0..3 : 16 f rows each
    const int wn = warp & 1;    // 0..1 : 64 hw cols each
    uint32_t af[4][4];
    {
        const float* Wb = expert_w + (size_t)e * 4096;
        int r0 = wf * 16 + (lane >> 2);
        int kA = (lane & 3) * 2;
        #pragma unroll
        for (int kt = 0; kt < 4; kt++) {
            int k0 = kt * 16 + kA;
            float2 w0 = *(const float2*)(Wb + r0 * 64 + k0);
            float2 w1 = *(const float2*)(Wb + (r0 + 8) * 64 + k0);
            float2 w2 = *(const float2*)(Wb + r0 * 64 + k0 + 8);
            float2 w3 = *(const float2*)(Wb + (r0 + 8) * 64 + k0 + 8);
            af[kt][0] = pack_f16x2(w0.x, w0.y);
            af[kt][1] = pack_f16x2(w1.x, w1.y);
            af[kt][2] = pack_f16x2(w2.x, w2.y);
            af[kt][3] = pack_f16x2(w3.x, w3.y);
        }
    }

    float acc2[8][4];
    #pragma unroll
    for (int nt = 0; nt < 8; nt++)
        #pragma unroll
        for (int qv = 0; qv < 4; qv++) acc2[nt][qv] = 0.f;

    const uint32_t sxb = smem_u32(sX);
    const uint32_t krow = (uint32_t)(lane & 15);
    #pragma unroll
    for (int kt = 0; kt < 4; kt++) {
        uint32_t kbase = ((uint32_t)(kt * 16) + krow) * (XPITCH * 4u);
        #pragma unroll
        for (int nt = 0; nt < 8; nt++) {
            uint32_t noff = (uint32_t)(wn * 64 + nt * 8) * 2u;
            uint32_t bf[2];
            LDMATRIX_X2T(bf, sxb + kbase + noff);
            MMA_F16(acc2[nt], af[kt], bf[0], bf[1]);
        }
    }

    // ---- epilogue: streaming stores ----
    float* outb = out + (size_t)b * CC * HWC + hw0;
    int f0 = wf * 16 + (lane >> 2);
    int cbase = wn * 64 + (lane & 3) * 2;
    #pragma unroll
    for (int nt = 0; nt < 8; nt++) {
        int cc = cbase + nt * 8;
        float2 v0 = make_float2(acc2[nt][0] * val, acc2[nt][1] * val);
        float2 v1 = make_float2(acc2[nt][2] * val, acc2[nt][3] * val);
        __stcs((float2*)(outb + (size_t)f0 * HWC + cc),       v0);
        __stcs((float2*)(outb + (size_t)(f0 + 8) * HWC + cc), v1);
    }
}

// ===========================================================================
extern "C" void kernel_launch(void* const* d_in, const int* in_sizes, int n_in,
                              void* d_out, int out_size) {
    const float* x = nullptr, *gate_w = nullptr, *gate_b = nullptr, *expert_w = nullptr;
    for (int i = 0; i < n_in; i++) {
        switch (in_sizes[i]) {
            case BB*CC*HH*WW: x        = (const float*)d_in[i]; break;  // 524288
            case EE*CC*3*3:   gate_w   = (const float*)d_in[i]; break;  // 4608
            case EE:          gate_b   = (const float*)d_in[i]; break;  // 8
            case EE*CC*CC:    expert_w = (const float*)d_in[i]; break;  // 32768
            default: break;
        }
    }
    float* out = (float*)d_out;
    const int main_elems = BB * CC * HWC;
    int write_ew = (out_size >= main_elems + BB * EE) ? 1 : 0;

    zero_kernel<<<1, 32>>>();
    pipe_kernel<<<2048, 256>>>(x, expert_w, gate_w, gate_b, out, write_ew);
}